// round 1
// baseline (speedup 1.0000x reference)
#include <cuda_runtime.h>
#include <math.h>

#define NB    8
#define C     192
#define C2    384
#define C4    768
#define HEADS 4
#define HD    48
#define HW    128
#define NPIX  16384
#define GK    192
#define NSEG  16
#define SEGLEN (NPIX/NSEG)

// ---------------- scratch (static device memory; no allocation at runtime) ----------------
__device__ float g_avg[NB*C];
__device__ float g_mx [NB*C];
__device__ float g_cg [NB*C];
__device__ float g_sp [NB*2*NPIX];
__device__ float g_sg [NB*NPIX];
__device__ float g_weff[NB*C4*C];
__device__ float g_qkv [(size_t)NB*C4*NPIX];   // 402 MB
__device__ float g_dw  [(size_t)NB*C4*NPIX];   // 402 MB
__device__ float g_inq [NB*C];
__device__ float g_ink [NB*C];
__device__ float g_spart[(size_t)NB*HEADS*NSEG*HD*HD];
__device__ float g_attn [(size_t)NB*HEADS*HD*HD];
__device__ float g_outg [(size_t)NB*C*NPIX];   // 100 MB

__device__ __forceinline__ float sigmoidf_(float x){ return 1.f/(1.f+expf(-x)); }

// ---------------- K1: per-(b,c) mean & max over pixels ----------------
__global__ void k_chan_pool(const float* __restrict__ x){
    int bc = blockIdx.x;
    const float4* px = (const float4*)(x + (size_t)bc*NPIX);
    int t = threadIdx.x;
    float s = 0.f, m = -1e30f;
    for (int i = t; i < NPIX/4; i += 256){
        float4 v = px[i];
        s += v.x+v.y+v.z+v.w;
        m = fmaxf(m, fmaxf(fmaxf(v.x,v.y), fmaxf(v.z,v.w)));
    }
    __shared__ float ss[256], sm[256];
    ss[t]=s; sm[t]=m; __syncthreads();
    for (int o=128;o>0;o>>=1){
        if (t<o){ ss[t]+=ss[t+o]; sm[t]=fmaxf(sm[t],sm[t+o]); }
        __syncthreads();
    }
    if (t==0){ g_avg[bc]=ss[0]*(1.f/NPIX); g_mx[bc]=sm[0]; }
}

// ---------------- K2: SE channel gate MLP ----------------
__global__ void k_chan_gate(const float* __restrict__ w1, const float* __restrict__ w2){
    int b = blockIdx.x, t = threadIdx.x;     // 192 threads
    __shared__ float pool[C2], sq[48];
    pool[t]     = g_avg[b*C+t];
    pool[C+t]   = g_mx [b*C+t];
    __syncthreads();
    if (t < 48){
        float a = 0.f;
        #pragma unroll 8
        for (int c=0;c<C2;c++) a += w1[t*C2+c]*pool[c];
        sq[t] = fmaxf(a, 0.f);
    }
    __syncthreads();
    float a = 0.f;
    #pragma unroll
    for (int s=0;s<48;s++) a += w2[t*48+s]*sq[s];
    g_cg[b*C+t] = sigmoidf_(a);
}

// ---------------- K3: per-pixel mean & max over channels ----------------
__global__ void k_spatial_stats(const float* __restrict__ x){
    int idx = blockIdx.x*256 + threadIdx.x;
    int b = idx >> 14, p = idx & (NPIX-1);
    const float* px = x + (size_t)b*C*NPIX + p;
    float s = 0.f, m = -1e30f;
    #pragma unroll 4
    for (int c=0;c<C;c++){ float v = px[(size_t)c*NPIX]; s += v; m = fmaxf(m, v); }
    g_sp[(size_t)b*2*NPIX + p]        = s*(1.f/C);
    g_sp[(size_t)b*2*NPIX + NPIX + p] = m;
}

// ---------------- K4: 7x7 spatial conv + sigmoid ----------------
__global__ void k_spatial_conv(const float* __restrict__ ws){
    int idx = blockIdx.x*256 + threadIdx.x;
    int b = idx >> 14, p = idx & (NPIX-1);
    int y = p >> 7, xx = p & 127;
    float acc = 0.f;
    #pragma unroll
    for (int ch=0; ch<2; ch++){
        const float* base = g_sp + (size_t)b*2*NPIX + (size_t)ch*NPIX;
        #pragma unroll
        for (int dy=-3; dy<=3; dy++){
            int yy = y+dy;
            if ((unsigned)yy < 128u){
                const float* row = base + yy*HW;
                #pragma unroll
                for (int dx=-3; dx<=3; dx++){
                    int xc = xx+dx;
                    if ((unsigned)xc < 128u)
                        acc += row[xc]*__ldg(&ws[ch*49 + (dy+3)*7 + (dx+3)]);
                }
            }
        }
    }
    g_sg[(size_t)b*NPIX + p] = sigmoidf_(acc);
}

// ---------------- K5: fold channel gate into qkv weights ----------------
__global__ void k_weff(const float* __restrict__ wq){
    int idx = blockIdx.x*256 + threadIdx.x;   // NB*C4*C
    int b = idx/(C4*C);
    int r = idx - b*C4*C;
    int c = r % C;
    g_weff[idx] = wq[r]*g_cg[b*C+c];
}

// ---------------- GEMM: C[o,p] = (scale?)(p) * sum_{c<192} A[o,c]*B[c,p] ----------------
// 64x64 block tile, 256 threads, 4x4 per thread, K staged in 48-chunks.
__global__ void k_gemm64(const float* __restrict__ A, long sA,
                         const float* __restrict__ B, long sB,
                         float* __restrict__ Cc, long sC,
                         int M, int P,
                         const float* __restrict__ S){
    int b  = blockIdx.z;
    A += (size_t)b*sA; B += (size_t)b*sB; Cc += (size_t)b*sC;
    int bo = blockIdx.y*64, bp = blockIdx.x*64;
    __shared__ float As[48][64];
    __shared__ float Bs[48][64];
    int tid = threadIdx.x;
    int tx = tid & 15, ty = tid >> 4;
    int tx4 = tx*4, ty4 = ty*4;
    float acc[4][4] = {};
    for (int c0 = 0; c0 < GK; c0 += 48){
        for (int e = tid; e < 64*48; e += 256){
            int o = e/48, k = e - o*48;
            As[k][o] = A[(size_t)(bo+o)*GK + c0 + k];
        }
        for (int e = tid; e < 48*64; e += 256){
            int k = e >> 6, p = e & 63;
            Bs[k][p] = B[(size_t)(c0+k)*P + bp + p];
        }
        __syncthreads();
        #pragma unroll
        for (int k = 0; k < 48; k++){
            float a0=As[k][ty4+0], a1=As[k][ty4+1], a2=As[k][ty4+2], a3=As[k][ty4+3];
            float b0=Bs[k][tx4+0], b1=Bs[k][tx4+1], b2=Bs[k][tx4+2], b3=Bs[k][tx4+3];
            acc[0][0]+=a0*b0; acc[0][1]+=a0*b1; acc[0][2]+=a0*b2; acc[0][3]+=a0*b3;
            acc[1][0]+=a1*b0; acc[1][1]+=a1*b1; acc[1][2]+=a1*b2; acc[1][3]+=a1*b3;
            acc[2][0]+=a2*b0; acc[2][1]+=a2*b1; acc[2][2]+=a2*b2; acc[2][3]+=a2*b3;
            acc[3][0]+=a3*b0; acc[3][1]+=a3*b1; acc[3][2]+=a3*b2; acc[3][3]+=a3*b3;
        }
        __syncthreads();
    }
    #pragma unroll
    for (int i=0;i<4;i++){
        #pragma unroll
        for (int j=0;j<4;j++){
            int p = bp + tx4 + j;
            float v = acc[i][j];
            if (S) v *= S[(size_t)b*NPIX + p];
            Cc[(size_t)(bo+ty4+i)*P + p] = v;
        }
    }
}

// ---------------- K7: depthwise 3x3, pad 1 ----------------
__global__ void k_dw(const float* __restrict__ wd){
    int bc = blockIdx.x;              // b*C4 + ch
    int ch = bc % C4;
    int y  = blockIdx.y;
    int xx = threadIdx.x;             // 128
    const float* in = g_qkv + (size_t)bc*NPIX;
    const float* w  = wd + ch*9;
    float acc = 0.f;
    #pragma unroll
    for (int dy=0; dy<3; dy++){
        int yy = y + dy - 1;
        if ((unsigned)yy < 128u){
            const float* row = in + yy*HW;
            #pragma unroll
            for (int dx=0; dx<3; dx++){
                int xc = xx + dx - 1;
                if ((unsigned)xc < 128u) acc += row[xc]*__ldg(&w[dy*3+dx]);
            }
        }
    }
    g_dw[(size_t)bc*NPIX + y*HW + xx] = acc;
}

// ---------------- K8: inverse L2 norms of q and k channels ----------------
__global__ void k_norm(){
    int id = blockIdx.x;              // NB*2*C
    int b = id/(2*C);
    int r = id - b*2*C;
    int which = r / C;                // 0 = q, 1 = k
    int c = r - which*C;
    const float4* p = (const float4*)(g_dw + ((size_t)b*C4 + (which?2*C:0) + c)*NPIX);
    int t = threadIdx.x;
    float s = 0.f;
    for (int i=t;i<NPIX/4;i+=256){ float4 v=p[i]; s += v.x*v.x+v.y*v.y+v.z*v.z+v.w*v.w; }
    __shared__ float sh[256];
    sh[t]=s; __syncthreads();
    for (int o=128;o>0;o>>=1){ if(t<o) sh[t]+=sh[t+o]; __syncthreads(); }
    if (t==0){
        float n = fmaxf(sqrtf(sh[0]), 1e-12f);
        (which ? g_ink : g_inq)[b*C+c] = 1.f/n;
    }
}

// ---------------- K9: partial q·k^T over a spatial segment ----------------
__global__ void k_attn_partial(){
    int bh  = blockIdx.x;             // b*HEADS + h
    int seg = blockIdx.y;
    int b = bh >> 2, hh = bh & 3;
    const float* qb = g_dw + ((size_t)b*C4 + hh*HD)*NPIX;
    const float* kb = g_dw + ((size_t)b*C4 + 2*C + hh*HD)*NPIX;
    __shared__ float qs[HD][65], ks[HD][65];
    int tid = threadIdx.x;
    int tx = tid & 15, ty = tid >> 4;
    float acc[3][3] = {};
    int p0 = seg*SEGLEN;
    for (int ck=0; ck<SEGLEN; ck+=64){
        for (int e=tid; e<HD*64; e+=256){
            int i = e >> 6, p = e & 63;
            qs[i][p] = qb[(size_t)i*NPIX + p0 + ck + p];
            ks[i][p] = kb[(size_t)i*NPIX + p0 + ck + p];
        }
        __syncthreads();
        #pragma unroll 8
        for (int p=0;p<64;p++){
            float q0=qs[ty*3+0][p], q1=qs[ty*3+1][p], q2=qs[ty*3+2][p];
            float k0=ks[tx*3+0][p], k1=ks[tx*3+1][p], k2=ks[tx*3+2][p];
            acc[0][0]+=q0*k0; acc[0][1]+=q0*k1; acc[0][2]+=q0*k2;
            acc[1][0]+=q1*k0; acc[1][1]+=q1*k1; acc[1][2]+=q1*k2;
            acc[2][0]+=q2*k0; acc[2][1]+=q2*k1; acc[2][2]+=q2*k2;
        }
        __syncthreads();
    }
    #pragma unroll
    for (int r=0;r<3;r++)
        #pragma unroll
        for (int s=0;s<3;s++)
            g_spart[((size_t)(bh*NSEG+seg)*HD + ty*3+r)*HD + tx*3+s] = acc[r][s];
}

// ---------------- K10: combine partials, scale, softmax ----------------
__global__ void k_softmax(const float* __restrict__ temp){
    int row = blockIdx.x;             // NB*HEADS*HD
    int bh = row / HD;
    int i  = row - bh*HD;
    int b = bh >> 2, hh = bh & 3;
    int j = threadIdx.x;              // 64
    float v = -1e30f;
    if (j < HD){
        float s = 0.f;
        #pragma unroll
        for (int sg=0; sg<NSEG; sg++)
            s += g_spart[((size_t)(bh*NSEG+sg)*HD + i)*HD + j];
        v = s * __ldg(&temp[hh]) * g_inq[b*C + hh*HD + i] * g_ink[b*C + hh*HD + j];
    }
    __shared__ float sh[64];
    sh[j] = v; __syncthreads();
    for (int o=32;o>0;o>>=1){ if (j<o) sh[j]=fmaxf(sh[j],sh[j+o]); __syncthreads(); }
    float m = sh[0]; __syncthreads();
    float e = (j < HD) ? expf(v - m) : 0.f;
    sh[j] = e; __syncthreads();
    for (int o=32;o>0;o>>=1){ if (j<o) sh[j]+=sh[j+o]; __syncthreads(); }
    if (j < HD) g_attn[(size_t)bh*HD*HD + i*HD + j] = e / sh[0];
}

// ---------------- K11: out = (attn @ v) * sigmoid(gate) ----------------
__global__ void k_av_gate(){
    int bh = blockIdx.x;
    int b = bh >> 2, hh = bh & 3;
    int p = blockIdx.y*128 + threadIdx.x;
    __shared__ float at[HD][HD];
    for (int e=threadIdx.x; e<HD*HD; e+=128)
        at[e/HD][e%HD] = g_attn[(size_t)bh*HD*HD + e];
    __syncthreads();
    const float* vb = g_dw + ((size_t)b*C4 + 3*C + hh*HD)*NPIX + p;
    const float* gb = g_dw + ((size_t)b*C4 + 1*C + hh*HD)*NPIX + p;
    float* ob = g_outg + ((size_t)b*C + hh*HD)*NPIX + p;
    float vcol[HD];
    #pragma unroll
    for (int j=0;j<HD;j++) vcol[j] = vb[(size_t)j*NPIX];
    for (int i=0;i<HD;i++){
        float a = 0.f;
        #pragma unroll
        for (int j=0;j<HD;j++) a += at[i][j]*vcol[j];
        float g = gb[(size_t)i*NPIX];
        ob[(size_t)i*NPIX] = a * sigmoidf_(g);
    }
}

// ---------------- host ----------------
extern "C" void kernel_launch(void* const* d_in, const int* in_sizes, int n_in,
                              void* d_out, int out_size){
    const float* x      = (const float*)d_in[0];
    const float* w_fc1  = (const float*)d_in[1];
    const float* w_fc2  = (const float*)d_in[2];
    const float* w_sp   = (const float*)d_in[3];
    const float* w_qkv  = (const float*)d_in[4];
    const float* w_dw   = (const float*)d_in[5];
    const float* w_proj = (const float*)d_in[6];
    const float* temp   = (const float*)d_in[7];
    float* out = (float*)d_out;

    float *weff, *qkv, *outg, *sg;
    cudaGetSymbolAddress((void**)&weff, g_weff);
    cudaGetSymbolAddress((void**)&qkv,  g_qkv);
    cudaGetSymbolAddress((void**)&outg, g_outg);
    cudaGetSymbolAddress((void**)&sg,   g_sg);

    k_chan_pool    <<<NB*C, 256>>>(x);
    k_chan_gate    <<<NB, 192>>>(w_fc1, w_fc2);
    k_spatial_stats<<<NB*NPIX/256, 256>>>(x);
    k_spatial_conv <<<NB*NPIX/256, 256>>>(w_sp);
    k_weff         <<<NB*C4*C/256, 256>>>(w_qkv);

    // qkv = sg(p) * (w_eff @ x)
    k_gemm64<<<dim3(NPIX/64, C4/64, NB), 256>>>(
        weff, (long)C4*C, x, (long)C*NPIX, qkv, (long)C4*NPIX, C4, NPIX, sg);

    k_dw<<<dim3(NB*C4, HW), 128>>>(w_dw);

    k_norm        <<<NB*2*C, 256>>>();
    k_attn_partial<<<dim3(NB*HEADS, NSEG), 256>>>();
    k_softmax     <<<NB*HEADS*HD, 64>>>(temp);
    k_av_gate     <<<dim3(NB*HEADS, NPIX/128), 128>>>();

    // final projection straight into d_out
    k_gemm64<<<dim3(NPIX/64, C/64, NB), 256>>>(
        w_proj, 0, outg, (long)C*NPIX, out, (long)C*NPIX, C, NPIX, nullptr);
}

// round 3
// speedup vs baseline: 1.9765x; 1.9765x over previous
#include <cuda_runtime.h>
#include <cuda_bf16.h>
#include <math.h>
#include <stdint.h>

#define NB    8
#define C     192
#define C2    384
#define C4    768
#define HEADS 4
#define HD    48
#define HW    128
#define NPIX  16384
#define GK    192
#define NSEG  16
#define SEGLEN (NPIX/NSEG)

// ---------------- scratch (static device memory) ----------------
__device__ float g_avg[NB*C];
__device__ float g_mx [NB*C];
__device__ float g_cg [NB*C];
__device__ float g_sp [NB*2*NPIX];
__device__ float g_sg [NB*NPIX];
__device__ float g_qkv [(size_t)NB*C4*NPIX];  // 402 MB
__device__ float g_dw  [(size_t)NB*C4*NPIX];  // 402 MB
__device__ float g_inq [NB*C];
__device__ float g_ink [NB*C];
__device__ float g_spart[(size_t)NB*HEADS*NSEG*HD*HD];
__device__ float g_attn [(size_t)NB*HEADS*HD*HD];
__device__ float g_outg [(size_t)NB*C*NPIX];  // 100 MB

__device__ __forceinline__ float sigmoidf_(float x){ return 1.f/(1.f+expf(-x)); }

// ---------------- K1: per-(b,c) mean & max over pixels ----------------
__global__ void k_chan_pool(const float* __restrict__ x){
    int bc = blockIdx.x;
    const float4* px = (const float4*)(x + (size_t)bc*NPIX);
    int t = threadIdx.x;
    float s = 0.f, m = -1e30f;
    for (int i = t; i < NPIX/4; i += 256){
        float4 v = px[i];
        s += v.x+v.y+v.z+v.w;
        m = fmaxf(m, fmaxf(fmaxf(v.x,v.y), fmaxf(v.z,v.w)));
    }
    __shared__ float ss[256], sm[256];
    ss[t]=s; sm[t]=m; __syncthreads();
    for (int o=128;o>0;o>>=1){
        if (t<o){ ss[t]+=ss[t+o]; sm[t]=fmaxf(sm[t],sm[t+o]); }
        __syncthreads();
    }
    if (t==0){ g_avg[bc]=ss[0]*(1.f/NPIX); g_mx[bc]=sm[0]; }
}

// ---------------- K2: SE channel gate MLP ----------------
__global__ void k_chan_gate(const float* __restrict__ w1, const float* __restrict__ w2){
    int b = blockIdx.x, t = threadIdx.x;     // 192 threads
    __shared__ float pool[C2], sq[48];
    pool[t]     = g_avg[b*C+t];
    pool[C+t]   = g_mx [b*C+t];
    __syncthreads();
    if (t < 48){
        float a = 0.f;
        #pragma unroll 8
        for (int c=0;c<C2;c++) a += w1[t*C2+c]*pool[c];
        sq[t] = fmaxf(a, 0.f);
    }
    __syncthreads();
    float a = 0.f;
    #pragma unroll
    for (int s=0;s<48;s++) a += w2[t*48+s]*sq[s];
    g_cg[b*C+t] = sigmoidf_(a);
}

// ---------------- K3: per-pixel mean & max over channels ----------------
__global__ void k_spatial_stats(const float* __restrict__ x){
    int idx = blockIdx.x*256 + threadIdx.x;
    int b = idx >> 14, p = idx & (NPIX-1);
    const float* px = x + (size_t)b*C*NPIX + p;
    float s = 0.f, m = -1e30f;
    #pragma unroll 4
    for (int c=0;c<C;c++){ float v = px[(size_t)c*NPIX]; s += v; m = fmaxf(m, v); }
    g_sp[(size_t)b*2*NPIX + p]        = s*(1.f/C);
    g_sp[(size_t)b*2*NPIX + NPIX + p] = m;
}

// ---------------- K4: 7x7 spatial conv + sigmoid ----------------
__global__ void k_spatial_conv(const float* __restrict__ ws){
    int idx = blockIdx.x*256 + threadIdx.x;
    int b = idx >> 14, p = idx & (NPIX-1);
    int y = p >> 7, xx = p & 127;
    float acc = 0.f;
    #pragma unroll
    for (int ch=0; ch<2; ch++){
        const float* base = g_sp + (size_t)b*2*NPIX + (size_t)ch*NPIX;
        #pragma unroll
        for (int dy=-3; dy<=3; dy++){
            int yy = y+dy;
            if ((unsigned)yy < 128u){
                const float* row = base + yy*HW;
                #pragma unroll
                for (int dx=-3; dx<=3; dx++){
                    int xc = xx+dx;
                    if ((unsigned)xc < 128u)
                        acc += row[xc]*__ldg(&ws[ch*49 + (dy+3)*7 + (dx+3)]);
                }
            }
        }
    }
    g_sg[(size_t)b*NPIX + p] = sigmoidf_(acc);
}

// ================= split-bf16 HMMA GEMM =================
// C[m,n] = S(n) * sum_k (A[m,k]*gate(k)) * B[k,n], K=GK=192, N stride NPIX.
// 3-pass split bf16 (AhBh + AhBl + AlBh) for ~fp32 accuracy.
// CTA: 128x128 tile, 8 warps of 64x32. K chunks of 48.
#define KC     48
#define APITCH 56          // bf16 units (112 B) -> conflict-free fragment LDS
#define SM_AH  0
#define SM_AL  14336
#define SM_BH  28672
#define SM_BL  43008
#define SMEM_HMMA 57344

__device__ __forceinline__ void mma16816(float* c, uint32_t a0, uint32_t a1,
                                         uint32_t a2, uint32_t a3,
                                         uint32_t b0, uint32_t b1){
    asm volatile(
      "mma.sync.aligned.m16n8k16.row.col.f32.bf16.bf16.f32 "
      "{%0,%1,%2,%3},{%4,%5,%6,%7},{%8,%9},{%0,%1,%2,%3};"
      : "+f"(c[0]), "+f"(c[1]), "+f"(c[2]), "+f"(c[3])
      : "r"(a0), "r"(a1), "r"(a2), "r"(a3), "r"(b0), "r"(b1));
}
__device__ __forceinline__ uint32_t pack_hi(float v0, float v1){
    __nv_bfloat162 h = __floats2bfloat162_rn(v0, v1);
    return *(uint32_t*)&h;
}

__global__ __launch_bounds__(256)
void k_hmma(const float* __restrict__ A,     // [M,GK] row-major (batch-shared)
            const float* __restrict__ gate,  // per-batch [GK] or null (stride C)
            const float* __restrict__ B,     // per-batch [GK,NPIX]
            long sB,
            float* __restrict__ Cout, long sC,
            const float* __restrict__ S,     // per-batch [NPIX] or null
            int M){
    extern __shared__ __align__(16) char smem[];
    uint32_t* Ah = (uint32_t*)(smem + SM_AH);
    uint32_t* Al = (uint32_t*)(smem + SM_AL);
    uint32_t* Bh = (uint32_t*)(smem + SM_BH);
    uint32_t* Bl = (uint32_t*)(smem + SM_BL);

    int b  = blockIdx.z;
    int bm = blockIdx.y*128, bn = blockIdx.x*128;
    B    += (size_t)b*sB;
    Cout += (size_t)b*sC;
    const float* gt = gate ? gate + b*C : nullptr;
    const float* Sp = S    ? S + (size_t)b*NPIX : nullptr;

    int tid = threadIdx.x, wid = tid>>5, lid = tid&31;
    int wr = wid>>2, wc = wid&3;
    int gi = lid>>2, li4 = lid&3;

    float acc[4][4][4];
    #pragma unroll
    for (int i=0;i<4;i++)
        #pragma unroll
        for (int j=0;j<4;j++)
            #pragma unroll
            for (int r=0;r<4;r++) acc[i][j][r]=0.f;

    for (int c0=0; c0<GK; c0+=KC){
        // ---- stage A chunk (gate-folded, split hi/lo) ----
        for (int q=tid; q<128*(KC/4); q+=256){
            int r  = q/(KC/4);
            int kq = (q - r*(KC/4))*4;
            int m  = bm + r; if (m >= M) m = M-1;
            float4 v = *(const float4*)&A[(size_t)m*GK + c0 + kq];
            if (gt){
                v.x *= gt[c0+kq]; v.y *= gt[c0+kq+1];
                v.z *= gt[c0+kq+2]; v.w *= gt[c0+kq+3];
            }
            uint32_t h0 = pack_hi(v.x, v.y), h1 = pack_hi(v.z, v.w);
            __nv_bfloat162 hh0 = *(__nv_bfloat162*)&h0;
            __nv_bfloat162 hh1 = *(__nv_bfloat162*)&h1;
            uint32_t l0 = pack_hi(v.x - __bfloat162float(hh0.x), v.y - __bfloat162float(hh0.y));
            uint32_t l1 = pack_hi(v.z - __bfloat162float(hh1.x), v.w - __bfloat162float(hh1.y));
            int o = (r*APITCH + kq)>>1;   // uint32 index
            Ah[o]=h0; Ah[o+1]=h1; Al[o]=l0; Al[o+1]=l1;
        }
        // ---- stage B chunk transposed to [n][k], split hi/lo ----
        for (int q=tid; q<128*(KC/4); q+=256){
            int n  = q & 127;
            int kq = (q >> 7)*4;
            const float* bp = B + (size_t)(c0+kq)*NPIX + bn + n;
            float v0 = bp[0], v1 = bp[NPIX], v2 = bp[2*NPIX], v3 = bp[3*NPIX];
            uint32_t h0 = pack_hi(v0, v1), h1 = pack_hi(v2, v3);
            __nv_bfloat162 hh0 = *(__nv_bfloat162*)&h0;
            __nv_bfloat162 hh1 = *(__nv_bfloat162*)&h1;
            uint32_t l0 = pack_hi(v0 - __bfloat162float(hh0.x), v1 - __bfloat162float(hh0.y));
            uint32_t l1 = pack_hi(v2 - __bfloat162float(hh1.x), v3 - __bfloat162float(hh1.y));
            int o = (n*APITCH + kq)>>1;
            Bh[o]=h0; Bh[o+1]=h1; Bl[o]=l0; Bl[o+1]=l1;
        }
        __syncthreads();

        const uint32_t* Ab = Ah + ((wr*64 + gi)*APITCH>>1) + li4;
        const uint32_t* Lb = Al + ((wr*64 + gi)*APITCH>>1) + li4;
        const uint32_t* Bb = Bh + ((wc*32 + gi)*APITCH>>1) + li4;
        const uint32_t* Mb = Bl + ((wc*32 + gi)*APITCH>>1) + li4;

        #pragma unroll
        for (int ks=0; ks<KC/16; ks++){
            int ko = ks*8;
            uint32_t bh[4][2], af[4][4];
            #pragma unroll
            for (int ni=0; ni<4; ni++){
                bh[ni][0] = Bb[ni*8*(APITCH>>1) + ko];
                bh[ni][1] = Bb[ni*8*(APITCH>>1) + ko + 4];
            }
            #pragma unroll
            for (int mi=0; mi<4; mi++){
                const uint32_t* ap = Ab + mi*16*(APITCH>>1) + ko;
                af[mi][0]=ap[0]; af[mi][1]=ap[8*(APITCH>>1)];
                af[mi][2]=ap[4]; af[mi][3]=ap[8*(APITCH>>1)+4];
            }
            #pragma unroll
            for (int mi=0; mi<4; mi++)
                #pragma unroll
                for (int ni=0; ni<4; ni++)
                    mma16816(acc[mi][ni], af[mi][0],af[mi][1],af[mi][2],af[mi][3],
                             bh[ni][0], bh[ni][1]);
            // A_hi * B_lo
            #pragma unroll
            for (int ni=0; ni<4; ni++){
                uint32_t b0 = Mb[ni*8*(APITCH>>1) + ko];
                uint32_t b1 = Mb[ni*8*(APITCH>>1) + ko + 4];
                #pragma unroll
                for (int mi=0; mi<4; mi++)
                    mma16816(acc[mi][ni], af[mi][0],af[mi][1],af[mi][2],af[mi][3], b0, b1);
            }
            // A_lo * B_hi
            #pragma unroll
            for (int mi=0; mi<4; mi++){
                const uint32_t* ap = Lb + mi*16*(APITCH>>1) + ko;
                uint32_t a0=ap[0], a1=ap[8*(APITCH>>1)], a2=ap[4], a3=ap[8*(APITCH>>1)+4];
                #pragma unroll
                for (int ni=0; ni<4; ni++)
                    mma16816(acc[mi][ni], a0,a1,a2,a3, bh[ni][0], bh[ni][1]);
            }
        }
        __syncthreads();
    }

    // ---- epilogue ----
    #pragma unroll
    for (int ni=0; ni<4; ni++){
        int n = bn + wc*32 + ni*8 + li4*2;
        float2 sv = Sp ? *(const float2*)&Sp[n] : make_float2(1.f,1.f);
        #pragma unroll
        for (int mi=0; mi<4; mi++){
            int m0 = bm + wr*64 + mi*16 + gi;
            if (m0 < M){
                float2 p = make_float2(acc[mi][ni][0]*sv.x, acc[mi][ni][1]*sv.y);
                *(float2*)&Cout[(size_t)m0*NPIX + n] = p;
            }
            int m1 = m0 + 8;
            if (m1 < M){
                float2 p = make_float2(acc[mi][ni][2]*sv.x, acc[mi][ni][3]*sv.y);
                *(float2*)&Cout[(size_t)m1*NPIX + n] = p;
            }
        }
    }
}

// ---------------- K8: depthwise 3x3, pad 1 ----------------
__global__ void k_dw(const float* __restrict__ wd){
    int bc = blockIdx.x;              // b*C4 + ch
    int ch = bc % C4;
    int y  = blockIdx.y;
    int xx = threadIdx.x;             // 128
    const float* in = g_qkv + (size_t)bc*NPIX;
    const float* w  = wd + ch*9;
    float acc = 0.f;
    #pragma unroll
    for (int dy=0; dy<3; dy++){
        int yy = y + dy - 1;
        if ((unsigned)yy < 128u){
            const float* row = in + yy*HW;
            #pragma unroll
            for (int dx=0; dx<3; dx++){
                int xc = xx + dx - 1;
                if ((unsigned)xc < 128u) acc += row[xc]*__ldg(&w[dy*3+dx]);
            }
        }
    }
    g_dw[(size_t)bc*NPIX + y*HW + xx] = acc;
}

// ---------------- K9: inverse L2 norms of q and k channels ----------------
__global__ void k_norm(){
    int id = blockIdx.x;              // NB*2*C
    int b = id/(2*C);
    int r = id - b*2*C;
    int which = r / C;                // 0 = q, 1 = k
    int c = r - which*C;
    const float4* p = (const float4*)(g_dw + ((size_t)b*C4 + (which?2*C:0) + c)*NPIX);
    int t = threadIdx.x;
    float s = 0.f;
    for (int i=t;i<NPIX/4;i+=256){ float4 v=p[i]; s += v.x*v.x+v.y*v.y+v.z*v.z+v.w*v.w; }
    __shared__ float sh[256];
    sh[t]=s; __syncthreads();
    for (int o=128;o>0;o>>=1){ if(t<o) sh[t]+=sh[t+o]; __syncthreads(); }
    if (t==0){
        float n = fmaxf(sqrtf(sh[0]), 1e-12f);
        (which ? g_ink : g_inq)[b*C+c] = 1.f/n;
    }
}

// ---------------- K10: partial q.k^T over a spatial segment ----------------
__global__ void k_attn_partial(){
    int bh  = blockIdx.x;             // b*HEADS + h
    int seg = blockIdx.y;
    int b = bh >> 2, hh = bh & 3;
    const float* qb = g_dw + ((size_t)b*C4 + hh*HD)*NPIX;
    const float* kb = g_dw + ((size_t)b*C4 + 2*C + hh*HD)*NPIX;
    __shared__ float qs[HD][65], ks[HD][65];
    int tid = threadIdx.x;
    int tx = tid & 15, ty = tid >> 4;
    float acc[3][3] = {};
    int p0 = seg*SEGLEN;
    for (int ck=0; ck<SEGLEN; ck+=64){
        for (int e=tid; e<HD*64; e+=256){
            int i = e >> 6, p = e & 63;
            qs[i][p] = qb[(size_t)i*NPIX + p0 + ck + p];
            ks[i][p] = kb[(size_t)i*NPIX + p0 + ck + p];
        }
        __syncthreads();
        #pragma unroll 8
        for (int p=0;p<64;p++){
            float q0=qs[ty*3+0][p], q1=qs[ty*3+1][p], q2=qs[ty*3+2][p];
            float k0=ks[tx*3+0][p], k1=ks[tx*3+1][p], k2=ks[tx*3+2][p];
            acc[0][0]+=q0*k0; acc[0][1]+=q0*k1; acc[0][2]+=q0*k2;
            acc[1][0]+=q1*k0; acc[1][1]+=q1*k1; acc[1][2]+=q1*k2;
            acc[2][0]+=q2*k0; acc[2][1]+=q2*k1; acc[2][2]+=q2*k2;
        }
        __syncthreads();
    }
    #pragma unroll
    for (int r=0;r<3;r++)
        #pragma unroll
        for (int s=0;s<3;s++)
            g_spart[((size_t)(bh*NSEG+seg)*HD + ty*3+r)*HD + tx*3+s] = acc[r][s];
}

// ---------------- K11: combine partials, scale, softmax ----------------
__global__ void k_softmax(const float* __restrict__ temp){
    int row = blockIdx.x;             // NB*HEADS*HD
    int bh = row / HD;
    int i  = row - bh*HD;
    int b = bh >> 2, hh = bh & 3;
    int j = threadIdx.x;              // 64
    float v = -1e30f;
    if (j < HD){
        float s = 0.f;
        #pragma unroll
        for (int sg=0; sg<NSEG; sg++)
            s += g_spart[((size_t)(bh*NSEG+sg)*HD + i)*HD + j];
        v = s * __ldg(&temp[hh]) * g_inq[b*C + hh*HD + i] * g_ink[b*C + hh*HD + j];
    }
    __shared__ float sh[64];
    sh[j] = v; __syncthreads();
    for (int o=32;o>0;o>>=1){ if (j<o) sh[j]=fmaxf(sh[j],sh[j+o]); __syncthreads(); }
    float m = sh[0]; __syncthreads();
    float e = (j < HD) ? expf(v - m) : 0.f;
    sh[j] = e; __syncthreads();
    for (int o=32;o>0;o>>=1){ if (j<o) sh[j]+=sh[j+o]; __syncthreads(); }
    if (j < HD) g_attn[(size_t)bh*HD*HD + i*HD + j] = e / sh[0];
}

// ---------------- K12: out = (attn @ v) * sigmoid(gate) ----------------
__global__ void k_av_gate(){
    int bh = blockIdx.x;
    int b = bh >> 2, hh = bh & 3;
    int p = blockIdx.y*128 + threadIdx.x;
    __shared__ float at[HD][HD];
    for (int e=threadIdx.x; e<HD*HD; e+=128)
        at[e/HD][e%HD] = g_attn[(size_t)bh*HD*HD + e];
    __syncthreads();
    const float* vb = g_dw + ((size_t)b*C4 + 3*C + hh*HD)*NPIX + p;
    const float* gb = g_dw + ((size_t)b*C4 + 1*C + hh*HD)*NPIX + p;
    float* ob = g_outg + ((size_t)b*C + hh*HD)*NPIX + p;
    float vcol[HD];
    #pragma unroll
    for (int j=0;j<HD;j++) vcol[j] = vb[(size_t)j*NPIX];
    for (int i=0;i<HD;i++){
        float a = 0.f;
        #pragma unroll
        for (int j=0;j<HD;j++) a += at[i][j]*vcol[j];
        float g = gb[(size_t)i*NPIX];
        ob[(size_t)i*NPIX] = a * sigmoidf_(g);
    }
}

// ---------------- host ----------------
extern "C" void kernel_launch(void* const* d_in, const int* in_sizes, int n_in,
                              void* d_out, int out_size){
    const float* x      = (const float*)d_in[0];
    const float* w_fc1  = (const float*)d_in[1];
    const float* w_fc2  = (const float*)d_in[2];
    const float* w_sp   = (const float*)d_in[3];
    const float* w_qkv  = (const float*)d_in[4];
    const float* w_dw   = (const float*)d_in[5];
    const float* w_proj = (const float*)d_in[6];
    const float* temp   = (const float*)d_in[7];
    float* out = (float*)d_out;

    float *qkv, *outg, *cg, *sg;
    cudaGetSymbolAddress((void**)&qkv,  g_qkv);
    cudaGetSymbolAddress((void**)&outg, g_outg);
    cudaGetSymbolAddress((void**)&cg,   g_cg);
    cudaGetSymbolAddress((void**)&sg,   g_sg);

    cudaFuncSetAttribute(k_hmma, cudaFuncAttributeMaxDynamicSharedMemorySize, SMEM_HMMA);

    k_chan_pool    <<<NB*C, 256>>>(x);
    k_chan_gate    <<<NB, 192>>>(w_fc1, w_fc2);
    k_spatial_stats<<<NB*NPIX/256, 256>>>(x);
    k_spatial_conv <<<NB*NPIX/256, 256>>>(w_sp);

    // qkv = sg(p) * ((w_qkv * cg) @ x)   on tensor cores (split-bf16, 3 passes)
    k_hmma<<<dim3(NPIX/128, 6, NB), 256, SMEM_HMMA>>>(
        w_qkv, cg, x, (long)C*NPIX, qkv, (long)C4*NPIX, sg, C4);

    k_dw<<<dim3(NB*C4, HW), 128>>>(w_dw);

    k_norm        <<<NB*2*C, 256>>>();
    k_attn_partial<<<dim3(NB*HEADS, NSEG), 256>>>();
    k_softmax     <<<NB*HEADS*HD, 64>>>(temp);
    k_av_gate     <<<dim3(NB*HEADS, NPIX/128), 128>>>();

    // final projection straight into d_out
    k_hmma<<<dim3(NPIX/128, 2, NB), 256, SMEM_HMMA>>>(
        w_proj, nullptr, outg, (long)C*NPIX, out, (long)C*NPIX, nullptr, C);
}